// round 3
// baseline (speedup 1.0000x reference)
#include <cuda_runtime.h>
#include <cstdint>

// VoxelHashTable: 2-level hash-grid trilinear interpolation.
// Inputs (metadata order):
//   d_in[0] query_pts float32 (M,3)
//   d_in[1] feats0    float32 (n0,32)
//   d_in[2] feats1    float32 (n1,32)
//   d_in[3] h2v0      int32   (2^20,)
//   d_in[4] h2v1      int32   (2^20,)
// Output: float32 (M, 64)  [level0 feats | level1 feats]

#define TMASK 0xFFFFF        // TSIZE = 2^20; x mod 2^20 == x & TMASK for wrapped int32
#define P0 73856093
#define P1 19349669
#define P2 83492791

__global__ __launch_bounds__(256)
void voxel_hash_kernel(const float* __restrict__ q,
                       const float* __restrict__ feats0,
                       const float* __restrict__ feats1,
                       const int*   __restrict__ h2v0,
                       const int*   __restrict__ h2v1,
                       float* __restrict__ out,
                       int M)
{
    const int warp = (blockIdx.x * blockDim.x + threadIdx.x) >> 5;
    const int lane = threadIdx.x & 31;
    if (warp >= M) return;

    // Warp-uniform query load (broadcast within warp via L1)
    const float qx = q[warp * 3 + 0];
    const float qy = q[warp * 3 + 1];
    const float qz = q[warp * 3 + 2];

    int   vidx[16];
    float w[16];

    // ---- Phase 1: compute hashes + issue all 16 h2v gathers (max MLP) ----
    #pragma unroll
    for (int level = 0; level < 2; level++) {
        const float res = (level == 0) ? 0.12f : 0.24f;
        // IEEE division to match jnp exactly (floor boundary sensitivity)
        const float sx = qx / res;
        const float sy = qy / res;
        const float sz = qz / res;
        const float bfx = floorf(sx), bfy = floorf(sy), bfz = floorf(sz);
        const float fx = sx - bfx, fy = sy - bfy, fz = sz - bfz;
        const int bx = (int)bfx, by = (int)bfy, bz = (int)bfz;

        // precompute prime-multiplied base coords (int32 wrap == jax int32 wrap)
        const int hx0 = bx * P0,        hy0 = by * P1,        hz0 = bz * P2;
        const int hx1 = (bx + 1) * P0,  hy1 = (by + 1) * P1,  hz1 = (bz + 1) * P2;

        const int* __restrict__ h2v = (level == 0) ? h2v0 : h2v1;

        #pragma unroll
        for (int c = 0; c < 8; c++) {
            const int ox = (c >> 2) & 1, oy = (c >> 1) & 1, oz = c & 1;
            const int hv = ((ox ? hx1 : hx0) + (oy ? hy1 : hy0) + (oz ? hz1 : hz0)) & TMASK;
            vidx[level * 8 + c] = h2v[hv];   // warp-uniform broadcast load
            // weight product order matches jnp.prod: ((wx*wy)*wz)
            const float wx = ox ? fx : (1.0f - fx);
            const float wy = oy ? fy : (1.0f - fy);
            const float wz = oz ? fz : (1.0f - fz);
            w[level * 8 + c] = (wx * wy) * wz;
        }
    }

    // ---- Phase 2: gather feature rows (128B coalesced per corner) + FMA ----
    float acc0 = 0.0f, acc1 = 0.0f;

    #pragma unroll
    for (int c = 0; c < 8; c++) {
        const int v = vidx[c];
        if (v >= 0) {
            acc0 = fmaf(feats0[(size_t)v * 32 + lane], w[c], acc0);
        }
    }
    #pragma unroll
    for (int c = 0; c < 8; c++) {
        const int v = vidx[8 + c];
        if (v >= 0) {
            acc1 = fmaf(feats1[(size_t)v * 32 + lane], w[8 + c], acc1);
        }
    }

    float* o = out + (size_t)warp * 64;
    o[lane]      = acc0;
    o[lane + 32] = acc1;
}

extern "C" void kernel_launch(void* const* d_in, const int* in_sizes, int n_in,
                              void* d_out, int out_size)
{
    const float* q      = (const float*)d_in[0];
    const float* feats0 = (const float*)d_in[1];
    const float* feats1 = (const float*)d_in[2];
    const int*   h2v0   = (const int*)d_in[3];
    const int*   h2v1   = (const int*)d_in[4];
    float* out = (float*)d_out;

    const int M = in_sizes[0] / 3;           // 500000 queries
    const int threads = 256;                 // 8 warps/block, 1 warp per query
    const int warps_per_block = threads / 32;
    const int blocks = (M + warps_per_block - 1) / warps_per_block;

    voxel_hash_kernel<<<blocks, threads>>>(q, feats0, feats1, h2v0, h2v1, out, M);
}

// round 7
// speedup vs baseline: 2.2182x; 2.2182x over previous
#include <cuda_runtime.h>
#include <cstdint>

// VoxelHashTable: 2-level hash-grid trilinear interpolation.
// R4: 2 queries per warp. Phase 1 (hash/h2v/weight) distributed across 16 lanes
// per query (lane = (level<<3)|corner); phase 2 broadcasts (v,w) via shfl and
// gathers feature rows as float2 per lane (16 lanes cover the 128B row).
//
// Inputs: d_in[0] query_pts (M,3) f32; d_in[1] feats0 (n0,32) f32;
//         d_in[2] feats1 (n1,32) f32; d_in[3] h2v0 (2^20) i32; d_in[4] h2v1 (2^20) i32
// Output: f32 (M,64) = [level0 | level1]

#define TMASK 0xFFFFF
#define P0 73856093
#define P1 19349669
#define P2 83492791

__global__ __launch_bounds__(256)
void voxel_hash_kernel2(const float* __restrict__ q,
                        const float* __restrict__ feats0,
                        const float* __restrict__ feats1,
                        const int*   __restrict__ h2v0,
                        const int*   __restrict__ h2v1,
                        float* __restrict__ out,
                        int M)
{
    const int warp = (blockIdx.x * blockDim.x + threadIdx.x) >> 5;
    const int lane = threadIdx.x & 31;
    const int half = lane >> 4;          // which of the 2 queries in this warp
    const int qi   = warp * 2 + half;
    const int sub  = lane & 15;          // (level<<3) | corner
    const int level = sub >> 3;
    const int c     = sub & 7;

    const bool q_ok = qi < M;
    const int  qs   = q_ok ? qi : 0;

    // ---- Phase 1: this lane owns corner c of 'level' for its query ----
    const float res = level ? 0.24f : 0.12f;
    const float qx = q[qs*3 + 0];
    const float qy = q[qs*3 + 1];
    const float qz = q[qs*3 + 2];
    // IEEE round-to-nearest division (matches jnp q/res exactly)
    const float sx = __fdiv_rn(qx, res);
    const float sy = __fdiv_rn(qy, res);
    const float sz = __fdiv_rn(qz, res);
    const float bfx = floorf(sx), bfy = floorf(sy), bfz = floorf(sz);
    const float fx = sx - bfx, fy = sy - bfy, fz = sz - bfz;

    const int ox = (c >> 2) & 1, oy = (c >> 1) & 1, oz = c & 1;
    const int cx = (int)bfx + ox;
    const int cy = (int)bfy + oy;
    const int cz = (int)bfz + oz;
    // int32 wrap-multiply == jax int32; &TMASK == mod 2^20
    const int hv = (cx * P0 + cy * P1 + cz * P2) & TMASK;

    const int* __restrict__ h2v = level ? h2v1 : h2v0;
    int v = h2v[hv];

    const float wx = ox ? fx : (1.0f - fx);
    const float wy = oy ? fy : (1.0f - fy);
    const float wz = oz ? fz : (1.0f - fz);
    float w = (wx * wy) * wz;            // jnp.prod order
    if (v < 0) { w = 0.0f; v = 0; }      // branch-free invalid handling

    // ---- Phase 2: broadcast (v,w) per corner, gather float2 feature pairs ----
    const int base = lane & 16;          // shfl source base for this query's half
    const int ch   = sub;                // channel-pair index 0..15 (ch*2, ch*2+1)

    float2 acc0 = make_float2(0.0f, 0.0f);
    float2 acc1 = make_float2(0.0f, 0.0f);

    #pragma unroll
    for (int i = 0; i < 8; i++) {
        const int   vv = __shfl_sync(0xffffffffu, v, base + i);
        const float ww = __shfl_sync(0xffffffffu, w, base + i);
        const float2 f = *reinterpret_cast<const float2*>(feats0 + (size_t)vv * 32 + ch * 2);
        acc0.x = fmaf(f.x, ww, acc0.x);
        acc0.y = fmaf(f.y, ww, acc0.y);
    }
    #pragma unroll
    for (int i = 0; i < 8; i++) {
        const int   vv = __shfl_sync(0xffffffffu, v, base + 8 + i);
        const float ww = __shfl_sync(0xffffffffu, w, base + 8 + i);
        const float2 f = *reinterpret_cast<const float2*>(feats1 + (size_t)vv * 32 + ch * 2);
        acc1.x = fmaf(f.x, ww, acc1.x);
        acc1.y = fmaf(f.y, ww, acc1.y);
    }

    if (q_ok) {
        float* o = out + (size_t)qi * 64;
        *reinterpret_cast<float2*>(o + ch * 2)      = acc0;
        *reinterpret_cast<float2*>(o + 32 + ch * 2) = acc1;
    }
}

extern "C" void kernel_launch(void* const* d_in, const int* in_sizes, int n_in,
                              void* d_out, int out_size)
{
    const float* q      = (const float*)d_in[0];
    const float* feats0 = (const float*)d_in[1];
    const float* feats1 = (const float*)d_in[2];
    const int*   h2v0   = (const int*)d_in[3];
    const int*   h2v1   = (const int*)d_in[4];
    float* out = (float*)d_out;

    const int M = in_sizes[0] / 3;                 // 500000
    const int threads = 256;                       // 8 warps = 16 queries/block
    const int qpb = (threads / 32) * 2;
    const int blocks = (M + qpb - 1) / qpb;

    voxel_hash_kernel2<<<blocks, threads>>>(q, feats0, feats1, h2v0, h2v1, out, M);
}